// round 14
// baseline (speedup 1.0000x reference)
#include <cuda_runtime.h>
#include <cuda_fp16.h>
#include <math.h>
#include <stdint.h>

#define ALPHA 0.2f
#define LOG2E 1.44269504f
#define EXPSH 11.54156036f   // 8 * log2(e)

static const int Bq = 8, Nq = 1024, Fq = 256, Oq = 128, Hq = 8;

typedef unsigned long long u64;

// ---------------- f32x2 helpers (final fp32 gemm only) -----------------------
__device__ __forceinline__ u64 fma2(u64 a, u64 b, u64 c) {
    u64 d;
    asm("fma.rn.f32x2 %0, %1, %2, %3;" : "=l"(d) : "l"(a), "l"(b), "l"(c));
    return d;
}
__device__ __forceinline__ u64 splat2(float x) {
    u64 d;
    unsigned u = __float_as_uint(x);
    asm("mov.b64 %0, {%1, %1};" : "=l"(d) : "r"(u));
    return d;
}
__device__ __forceinline__ float2 unpack2(u64 v) {
    unsigned lo, hi;
    asm("mov.b64 {%0, %1}, %2;" : "=r"(lo), "=r"(hi) : "l"(v));
    return make_float2(__uint_as_float(lo), __uint_as_float(hi));
}
__device__ __forceinline__ float ex2a(float x) {
    float y;
    asm("ex2.approx.ftz.f32 %0, %1;" : "=f"(y) : "f"(x));
    return y;
}

// ---------------- tensor-core helpers ---------------------------------------
__device__ __forceinline__ void ldsm4(unsigned* r, const void* p) {
    unsigned a = (unsigned)__cvta_generic_to_shared(p);
    asm volatile("ldmatrix.sync.aligned.m8n8.x4.shared.b16 {%0,%1,%2,%3}, [%4];"
                 : "=r"(r[0]), "=r"(r[1]), "=r"(r[2]), "=r"(r[3]) : "r"(a));
}
__device__ __forceinline__ void mma16816(float* d, const unsigned* a,
                                         const unsigned* b, const float* c) {
    asm volatile(
        "mma.sync.aligned.m16n8k16.row.col.f32.f16.f16.f32 "
        "{%0,%1,%2,%3},{%4,%5,%6,%7},{%8,%9},{%10,%11,%12,%13};"
        : "=f"(d[0]), "=f"(d[1]), "=f"(d[2]), "=f"(d[3])
        : "r"(a[0]), "r"(a[1]), "r"(a[2]), "r"(a[3]), "r"(b[0]), "r"(b[1]),
          "f"(c[0]), "f"(c[1]), "f"(c[2]), "f"(c[3]));
}
__device__ __forceinline__ void cpa16(void* smem_dst, const void* gsrc) {
    unsigned a = (unsigned)__cvta_generic_to_shared(smem_dst);
    asm volatile("cp.async.ca.shared.global [%0], [%1], 16;" :: "r"(a), "l"(gsrc));
}
__device__ __forceinline__ void cpa_commit() {
    asm volatile("cp.async.commit_group;" ::: "memory");
}
__device__ __forceinline__ void cpa_wait0() {
    asm volatile("cp.async.wait_group 0;" ::: "memory");
}

// ---------------- scratch ----------------------------------------------------
__device__ __half g_in16[(size_t)8192 * 256];
__device__ __half g_wattT[(size_t)8 * 128 * 256];
__device__ __half g_h1T[(size_t)64 * 128 * 1024];     // [z][o][j]
__device__ __half g_x1[(size_t)8192 * 1024];          // [b*N+n][h*O+o]
__device__ __half g_woutT[(size_t)128 * 1024];
__device__ __half g_linw16[(size_t)128 * 1024];
__device__ __half g_h2T[(size_t)8 * 128 * 1024];
__device__ float g_linp[(size_t)8192 * 128];
__device__ float g_att2[(size_t)8192 * 128];
__device__ float g_s1[(size_t)64 * 1024];
__device__ float g_s2[(size_t)64 * 1024];
__device__ float g_s1b[(size_t)8 * 1024];
__device__ float g_s2b[(size_t)8 * 1024];
__device__ float g_ln_wT[(size_t)128 * 128];
__device__ unsigned g_mask[(size_t)8 * 1024 * 32];    // adj bitmask, 1MB

// ---------------- mega prep: packadj || c2h(inputs) || weight prep -----------
__device__ __forceinline__ void t2h_body(const float* in, __half* out, int R,
                                         int C, int bx, int by, int tid,
                                         float* tbuf /*32*33*/) {
    int c0 = bx * 32, r0 = by * 32;
    int x = tid & 31, y = tid >> 5;
    for (int i = y; i < 32; i += 8)
        tbuf[i * 33 + x] = in[(size_t)(r0 + i) * C + c0 + x];
    __syncthreads();
    for (int i = y; i < 32; i += 8)
        out[(size_t)(c0 + i) * R + r0 + x] = __float2half_rn(tbuf[x * 33 + i]);
}

__global__ __launch_bounds__(256) void mega_prep_k(
    const int* __restrict__ adj, unsigned* __restrict__ mask,
    const float* __restrict__ inputs, __half* __restrict__ in16,
    const float* __restrict__ W_att, __half* __restrict__ wattT,
    const float* __restrict__ W_out, __half* __restrict__ woutT,
    const float* __restrict__ ln_w, float* __restrict__ ln_wT,
    const float* __restrict__ lin_w, __half* __restrict__ linw16) {
    __shared__ float tbuf[32 * 33];
    int bid = blockIdx.x, tid = threadIdx.x;
    if (bid < 2048) {
        int t = bid * 256 + tid;
        int lane = tid & 31;
        const int4* p = (const int4*)adj + (size_t)t * 4;
        int4 a = p[0], b = p[1], c = p[2], d = p[3];
        unsigned bits = (a.x > 0 ? 1u : 0u) | (a.y > 0 ? 2u : 0u) |
                        (a.z > 0 ? 4u : 0u) | (a.w > 0 ? 8u : 0u) |
                        (b.x > 0 ? 16u : 0u) | (b.y > 0 ? 32u : 0u) |
                        (b.z > 0 ? 64u : 0u) | (b.w > 0 ? 128u : 0u) |
                        (c.x > 0 ? 256u : 0u) | (c.y > 0 ? 512u : 0u) |
                        (c.z > 0 ? 1024u : 0u) | (c.w > 0 ? 2048u : 0u) |
                        (d.x > 0 ? 4096u : 0u) | (d.y > 0 ? 8192u : 0u) |
                        (d.z > 0 ? 16384u : 0u) | (d.w > 0 ? 32768u : 0u);
        unsigned r = bits << ((lane & 1) * 16);
        r |= __shfl_xor_sync(0xffffffffu, r, 1);
        if ((lane & 1) == 0) mask[t >> 1] = r;
    } else if (bid < 4096) {
        int i = (bid - 2048) * 256 + tid;
        float4 v = ((const float4*)inputs)[i];
        half2 a = __floats2half2_rn(v.x, v.y);
        half2 b = __floats2half2_rn(v.z, v.w);
        uint2 o;
        o.x = *(unsigned*)&a;
        o.y = *(unsigned*)&b;
        *(uint2*)(in16 + (size_t)i * 4) = o;
    } else {
        int pb = bid - 4096;   // 0..527
        if (pb < 256) {
            int z = pb >> 5, rem = pb & 31;
            t2h_body(W_att + (size_t)z * 256 * 128,
                     wattT + (size_t)z * 128 * 256, 256, 128, rem & 3,
                     rem >> 2, tid, tbuf);
        } else if (pb < 384) {
            int idx = pb - 256;
            t2h_body(W_out, woutT, 1024, 128, idx & 3, idx >> 2, tid, tbuf);
        } else if (pb < 400) {
            int idx = pb - 384;
            int bx = idx & 3, by = idx >> 2;
            int c0 = bx * 32, r0 = by * 32;
            int x = tid & 31, y = tid >> 5;
            for (int i = y; i < 32; i += 8)
                tbuf[i * 33 + x] = ln_w[(size_t)(r0 + i) * 128 + c0 + x];
            __syncthreads();
            for (int i = y; i < 32; i += 8)
                ln_wT[(size_t)(c0 + i) * 128 + r0 + x] = tbuf[x * 33 + i];
        } else {
            int i = (pb - 400) * 256 + tid;
            float4 v = ((const float4*)lin_w)[i];
            half2 a = __floats2half2_rn(v.x, v.y);
            half2 b = __floats2half2_rn(v.z, v.w);
            uint2 o;
            o.x = *(unsigned*)&a;
            o.y = *(unsigned*)&b;
            *(uint2*)(linw16 + (size_t)i * 4) = o;
        }
    }
}

// ---------------- tensor GEMM (mma.sync, cp.async double-buffered) ----------
// C = A @ Bt^T.  MODE 0: h1T 128x128 tiles (+fused s1/s2);
// MODE 1: h2T 128x32 tiles (+fused s1b/s2b); MODE 2: linp 32x128 (fp32 out)
template <int MODE>
__global__ __launch_bounds__(256) void tg_k(const __half* __restrict__ Aroot,
                                            const __half* __restrict__ Btroot,
                                            void* __restrict__ Croot,
                                            const float* __restrict__ asrc,
                                            const float* __restrict__ adst,
                                            float* __restrict__ s1g,
                                            float* __restrict__ s2g) {
    const int K = (MODE == 0) ? 256 : 1024;
    const int NIT = K / 64;
    const int TM = (MODE == 2) ? 32 : 128;
    const int TN = (MODE == 0) ? 128 : ((MODE == 1) ? 32 : 128);
    const int MW = TM / 32;
    const int NW = 8 / MW;
    const int NSP = TN / NW;
    const int N8 = NSP / 8;
    const int PAD = 72;
    extern __shared__ __half smh[];
    __half* As = smh;                    // 2 * TM*PAD
    __half* Bs = smh + 2 * TM * PAD;     // 2 * TN*PAD
    int tid = threadIdx.x, bx = blockIdx.x, z = blockIdx.z;

    const __half* A;
    const __half* Bt;
    __half* Ch = nullptr;
    float* Cf = nullptr;
    int lda, ldb, n0 = 0, hsel = 0;
    if (MODE == 0) {
        int b = z >> 3, h = z & 7;
        hsel = h;
        A = Aroot + (size_t)h * 128 * 256;
        lda = 256;
        Bt = Btroot + (size_t)b * 1024 * 256 + (size_t)bx * 128 * 256;
        ldb = 256;
        Ch = (__half*)Croot + (size_t)z * 131072;
        n0 = bx * 128;
    } else if (MODE == 1) {
        A = Aroot;
        lda = 1024;
        Bt = Btroot + (size_t)z * 1048576 + (size_t)bx * 32 * 1024;
        ldb = 1024;
        Ch = (__half*)Croot + (size_t)z * 131072;
        n0 = bx * 32;
    } else {
        A = Aroot + (size_t)bx * 32 * 1024;
        lda = 1024;
        Bt = Btroot;
        ldb = 1024;
        Cf = (float*)Croot + (size_t)bx * 32 * 128;
    }

    int w = tid >> 5, lane = tid & 31;
    int mw = w % MW, nw = w / MW;
    int wm = mw * 32, wn = nw * NSP;
    int ar = (lane & 7) | (((lane >> 3) & 1) << 3);
    int akh = (lane >> 4) << 3;
    int bn = ((lane >> 4) << 3) | (lane & 7);
    int bkh = ((lane >> 3) & 1) << 3;

    auto loadTiles = [&](int buf, int k0) {
        __half* ab = As + buf * TM * PAD;
        __half* bb = Bs + buf * TN * PAD;
#pragma unroll
        for (int q = 0; q < TM / 32; q++) {
            int f = tid + q * 256;
            int row = f >> 3, c8 = f & 7;
            cpa16(&ab[row * PAD + c8 * 8], A + (size_t)row * lda + k0 + c8 * 8);
        }
#pragma unroll
        for (int q = 0; q < TN / 32; q++) {
            int f = tid + q * 256;
            int row = f >> 3, c8 = f & 7;
            cpa16(&bb[row * PAD + c8 * 8], Bt + (size_t)row * ldb + k0 + c8 * 8);
        }
        cpa_commit();
    };

    float acc[2][N8][4];
#pragma unroll
    for (int mt = 0; mt < 2; mt++)
#pragma unroll
        for (int n8 = 0; n8 < N8; n8++)
#pragma unroll
            for (int e = 0; e < 4; e++) acc[mt][n8][e] = 0.f;

    loadTiles(0, 0);
    for (int it = 0; it < NIT; it++) {
        int cb = it & 1;
        cpa_wait0();
        __syncthreads();
        if (it + 1 < NIT) loadTiles(cb ^ 1, (it + 1) * 64);
        const __half* ab = As + cb * TM * PAD;
        const __half* bb = Bs + cb * TN * PAD;
#pragma unroll
        for (int kk = 0; kk < 64; kk += 16) {
            unsigned af[2][4], bf[N8 / 2][4];
            ldsm4(af[0], &ab[(wm + ar) * PAD + kk + akh]);
            ldsm4(af[1], &ab[(wm + 16 + ar) * PAD + kk + akh]);
#pragma unroll
            for (int np = 0; np < N8 / 2; np++)
                ldsm4(bf[np], &bb[(wn + np * 16 + bn) * PAD + kk + bkh]);
#pragma unroll
            for (int mt = 0; mt < 2; mt++)
#pragma unroll
                for (int n8 = 0; n8 < N8; n8++)
                    mma16816(acc[mt][n8], af[mt], &bf[n8 >> 1][(n8 & 1) * 2],
                             acc[mt][n8]);
        }
    }

    __syncthreads();
    int r0 = lane >> 2, cc = (lane & 3) * 2;

    // C stores
#pragma unroll
    for (int mt = 0; mt < 2; mt++)
#pragma unroll
        for (int n8 = 0; n8 < N8; n8++) {
            int row0 = wm + mt * 16 + r0;
            int col = wn + n8 * 8 + cc;
            if (MODE <= 1) {
                half2 lo = __floats2half2_rn(acc[mt][n8][0], acc[mt][n8][1]);
                half2 hi = __floats2half2_rn(acc[mt][n8][2], acc[mt][n8][3]);
                *(half2*)&Ch[(size_t)row0 * 1024 + n0 + col] = lo;
                *(half2*)&Ch[(size_t)(row0 + 8) * 1024 + n0 + col] = hi;
            } else {
                *(float2*)&Cf[(size_t)row0 * 128 + col] =
                    make_float2(acc[mt][n8][0], acc[mt][n8][1]);
                *(float2*)&Cf[(size_t)(row0 + 8) * 128 + col] =
                    make_float2(acc[mt][n8][2], acc[mt][n8][3]);
            }
        }

    // fused s1/s2 (MODE<=1): s[j] = LOG2E * sum_o a[o] * h[o][j]
    if (MODE <= 1) {
        float a1r[4], a2r[4];
        int rws[4] = {wm + r0, wm + r0 + 8, wm + 16 + r0, wm + 24 + r0};
#pragma unroll
        for (int q = 0; q < 4; q++) {
            a1r[q] = asrc[hsel * 128 + rws[q]] * LOG2E;
            a2r[q] = adst[hsel * 128 + rws[q]] * LOG2E;
        }
        float* red = (float*)smh;   // reuse smem
#pragma unroll
        for (int n8 = 0; n8 < N8; n8++) {
            float s1lo = a1r[0] * acc[0][n8][0] + a1r[1] * acc[0][n8][2] +
                         a1r[2] * acc[1][n8][0] + a1r[3] * acc[1][n8][2];
            float s1hi = a1r[0] * acc[0][n8][1] + a1r[1] * acc[0][n8][3] +
                         a1r[2] * acc[1][n8][1] + a1r[3] * acc[1][n8][3];
            float s2lo = a2r[0] * acc[0][n8][0] + a2r[1] * acc[0][n8][2] +
                         a2r[2] * acc[1][n8][0] + a2r[3] * acc[1][n8][2];
            float s2hi = a2r[0] * acc[0][n8][1] + a2r[1] * acc[0][n8][3] +
                         a2r[2] * acc[1][n8][1] + a2r[3] * acc[1][n8][3];
#pragma unroll
            for (int o = 4; o < 32; o <<= 1) {
                s1lo += __shfl_xor_sync(0xffffffffu, s1lo, o);
                s1hi += __shfl_xor_sync(0xffffffffu, s1hi, o);
                s2lo += __shfl_xor_sync(0xffffffffu, s2lo, o);
                s2hi += __shfl_xor_sync(0xffffffffu, s2hi, o);
            }
            if (lane < 4) {
                int col = wn + n8 * 8 + lane * 2;
                red[(mw * TN + col) * 2 + 0] = s1lo;
                red[(mw * TN + col) * 2 + 1] = s2lo;
                red[(mw * TN + col + 1) * 2 + 0] = s1hi;
                red[(mw * TN + col + 1) * 2 + 1] = s2hi;
            }
        }
        __syncthreads();
        if (tid < TN) {
            float s1 = 0.f, s2 = 0.f;
#pragma unroll
            for (int m = 0; m < MW; m++) {
                s1 += red[(m * TN + tid) * 2 + 0];
                s2 += red[(m * TN + tid) * 2 + 1];
            }
            s1g[(size_t)z * 1024 + n0 + tid] = s1;
            s2g[(size_t)z * 1024 + n0 + tid] = s2;
        }
    }
}

// ---------------- pipelined HMMA fused attention ------------------------------
// scores pre-scaled by log2e: p = bit ? ex2(lrelu(s1+s2) - 8*log2e) : 0
#define APAD 72
template <int MODE>
__global__ __launch_bounds__(256) void at_k(const __half* __restrict__ hT,
                                            const float* __restrict__ s1g,
                                            const float* __restrict__ s2g,
                                            const unsigned* __restrict__ mask,
                                            void* __restrict__ outp) {
    const int TM = (MODE == 0) ? 128 : 32;
    const int MW = TM / 32;
    const int NW = 8 / MW;
    const int NSP = 128 / NW;
    const int N8 = NSP / 8;
    const int SC = TM / 8;
    const int LOGSC = (MODE == 0) ? 4 : 2;

    extern __shared__ char smraw[];
    __half* Ps = (__half*)smraw;
    __half* Vs = Ps + 2 * TM * APAD;
    float* s1s = (float*)(Vs + 2 * 128 * APAD);
    float* ds = s1s + TM;
    float* s2s = ds + TM;

    int tid = threadIdx.x, bx = blockIdx.x, z = blockIdx.z;
    int b, h;
    if (MODE == 0) { b = z >> 3; h = z & 7; }
    else { b = z; h = 0; }
    int i0 = bx * TM;
    const __half* hz = hT + (size_t)z * 131072;
    const unsigned* maskb = mask + (size_t)b * 32768;

    ((float4*)s2s)[tid] = ((const float4*)(s2g + (size_t)z * 1024))[tid];
    if (tid < TM) s1s[tid] = s1g[(size_t)z * 1024 + i0 + tid];
    __syncthreads();

    int w = tid >> 5, lane = tid & 31;
    int mw = w % MW, nw = w / MW;
    int wm = mw * 32, wn = nw * NSP;
    int ar = (lane & 7) | (((lane >> 3) & 1) << 3);
    int akh = (lane >> 4) << 3;
    int bn = ((lane >> 4) << 3) | (lane & 7);
    int bkh = ((lane >> 3) & 1) << 3;

    float acc[2][N8][4];
#pragma unroll
    for (int mt = 0; mt < 2; mt++)
#pragma unroll
        for (int n8 = 0; n8 < N8; n8++)
#pragma unroll
            for (int e = 0; e < 4; e++) acc[mt][n8][e] = 0.f;
    float dl[SC];
#pragma unroll
    for (int s = 0; s < SC; s++) dl[s] = 0.f;

    int bitpos = (2 * lane) & 31;

    auto issueV = [&](int buf, int j0) {
        __half* vb = Vs + buf * 128 * APAD;
#pragma unroll
        for (int q = 0; q < 4; q++) {
            int f = tid + q * 256;
            int row = f >> 3, c8 = f & 7;
            cpa16(&vb[row * APAD + c8 * 8],
                  hz + (size_t)row * 1024 + j0 + c8 * 8);
        }
        cpa_commit();
    };
    auto loadMaskW = [&](int j0) -> unsigned {
        int s = lane & (SC - 1);
        int wsel = (lane >> LOGSC) & 1;
        return maskb[((size_t)(i0 + w + s * 8) << 5) + (j0 >> 5) + wsel];
    };
    auto buildP = [&](int buf, int j0, unsigned mpre) {
        __half* pb = Ps + buf * TM * APAD;
        float s2a = s2s[j0 + 2 * lane];
        float s2b = s2s[j0 + 2 * lane + 1];
#pragma unroll
        for (int s = 0; s < SC; s++) {
            int i = w + s * 8;
            unsigned m = __shfl_sync(0xffffffffu, mpre, ((lane >> 4) << LOGSC) | s);
            unsigned two = (m >> bitpos) & 3u;
            float s1v = s1s[i];
            float e1 = s1v + s2a;
            e1 = e1 > 0.f ? e1 : ALPHA * e1;
            float e2 = s1v + s2b;
            e2 = e2 > 0.f ? e2 : ALPHA * e2;
            float p1 = (two & 1u) ? ex2a(e1 - EXPSH) : 0.f;
            float p2 = (two & 2u) ? ex2a(e2 - EXPSH) : 0.f;
            *(half2*)&pb[i * APAD + 2 * lane] = __floats2half2_rn(p1, p2);
            dl[s] += p1 + p2;
        }
    };

    unsigned mpre = loadMaskW(0);
    issueV(0, 0);
    buildP(0, 0, mpre);

    for (int t = 0; t < 16; t++) {
        int cb = t & 1, nb = cb ^ 1;
        cpa_wait0();
        __syncthreads();
        if (t < 15) {
            issueV(nb, (t + 1) * 64);
            mpre = loadMaskW((t + 1) * 64);
        }
        const __half* pb = Ps + cb * TM * APAD;
        const __half* vb = Vs + cb * 128 * APAD;
#pragma unroll
        for (int kk = 0; kk < 64; kk += 16) {
            unsigned af[2][4], bf[N8 / 2][4];
            ldsm4(af[0], &pb[(wm + ar) * APAD + kk + akh]);
            ldsm4(af[1], &pb[(wm + 16 + ar) * APAD + kk + akh]);
#pragma unroll
            for (int np = 0; np < N8 / 2; np++)
                ldsm4(bf[np], &vb[(wn + np * 16 + bn) * APAD + kk + bkh]);
#pragma unroll
            for (int mt = 0; mt < 2; mt++)
#pragma unroll
                for (int n8 = 0; n8 < N8; n8++)
                    mma16816(acc[mt][n8], af[mt], &bf[n8 >> 1][(n8 & 1) * 2],
                             acc[mt][n8]);
        }
        if (t < 15) buildP(nb, (t + 1) * 64, mpre);
    }

#pragma unroll
    for (int s = 0; s < SC; s++) {
        float v = dl[s];
#pragma unroll
        for (int o = 16; o; o >>= 1) v += __shfl_xor_sync(0xffffffffu, v, o);
        if (lane == 0) ds[s * 8 + w] = v;
    }
    __syncthreads();

    int r0 = lane >> 2, cc = (lane & 3) * 2;
#pragma unroll
    for (int mt = 0; mt < 2; mt++)
#pragma unroll
        for (int n8 = 0; n8 < N8; n8++) {
            int row0 = wm + mt * 16 + r0, row1 = row0 + 8;
            int col = wn + n8 * 8 + cc;
            float inv0 = 1.f / ds[row0], inv1 = 1.f / ds[row1];
            float f0 = acc[mt][n8][0] * inv0, f1 = acc[mt][n8][1] * inv0;
            float f2 = acc[mt][n8][2] * inv1, f3 = acc[mt][n8][3] * inv1;
            if (MODE == 0) {
                f0 = f0 > 0.f ? f0 : expm1f(f0);
                f1 = f1 > 0.f ? f1 : expm1f(f1);
                f2 = f2 > 0.f ? f2 : expm1f(f2);
                f3 = f3 > 0.f ? f3 : expm1f(f3);
                __half* x1 = (__half*)outp;
                *(half2*)&x1[((size_t)b * 1024 + i0 + row0) * 1024 + h * 128 + col] =
                    __floats2half2_rn(f0, f1);
                *(half2*)&x1[((size_t)b * 1024 + i0 + row1) * 1024 + h * 128 + col] =
                    __floats2half2_rn(f2, f3);
            } else {
                float* o2 = (float*)outp;
                *(float2*)&o2[((size_t)b * 1024 + i0 + row0) * 128 + col] =
                    make_float2(f0, f1);
                *(float2*)&o2[((size_t)b * 1024 + i0 + row1) * 128 + col] =
                    make_float2(f2, f3);
            }
        }
}

// ---------------- final fp32 gemm: relu((linp+att2+lin_b) @ ln_wT + ln_b) ----
__global__ void __launch_bounds__(256)
final_k(const float* __restrict__ A0, const float* __restrict__ B0,
        float* __restrict__ C0, const float* __restrict__ add,
        const float* __restrict__ biasA, const float* __restrict__ biasC) {
    const int BK = 32, BM = 64, RM = 4;
    __shared__ float As[BK][BM + 4];
    __shared__ float Bs[BK][128 + 4];
    int mblk = blockIdx.x * BM;
    int tid = threadIdx.x;
    int tx = tid % 16, ty = tid / 16;
    u64 acc[RM][4];
#pragma unroll
    for (int r = 0; r < RM; r++)
#pragma unroll
        for (int c = 0; c < 4; c++) acc[r][c] = 0ull;

    for (int k0 = 0; k0 < 128; k0 += BK) {
#pragma unroll
        for (int q = 0; q < BM / 32; q++) {
            int f = tid + q * 256;
            int m = f >> 3;
            int kk = (f & 7) * 4;
            const float* ap = A0 + (size_t)(mblk + m) * 128 + (k0 + kk);
            const float* dp = add + (size_t)(mblk + m) * 128 + (k0 + kk);
            const float* bp = biasA + (k0 + kk);
            float4 v;
            v.x = ap[0] + dp[0] + bp[0];
            v.y = ap[1] + dp[1] + bp[1];
            v.z = ap[2] + dp[2] + bp[2];
            v.w = ap[3] + dp[3] + bp[3];
            As[kk + 0][m] = v.x;
            As[kk + 1][m] = v.y;
            As[kk + 2][m] = v.z;
            As[kk + 3][m] = v.w;
        }
#pragma unroll
        for (int q = 0; q < 4; q++) {
            int f = tid + q * 256;
            int kk = f >> 5;
            int nn = (f & 31) * 4;
            *(float4*)&Bs[kk][nn] = *(const float4*)(B0 + (size_t)(k0 + kk) * 128 + nn);
        }
        __syncthreads();
#pragma unroll 8
        for (int kk = 0; kk < BK; kk++) {
            u64 as_[RM];
            float4 av = *(const float4*)&As[kk][ty * RM];
            as_[0] = splat2(av.x);
            as_[1] = splat2(av.y);
            as_[2] = splat2(av.z);
            as_[3] = splat2(av.w);
            ulonglong2 b0 = *(const ulonglong2*)&Bs[kk][tx * 4];
            ulonglong2 b1 = *(const ulonglong2*)&Bs[kk][64 + tx * 4];
            u64 bs_[4] = {b0.x, b0.y, b1.x, b1.y};
#pragma unroll
            for (int r = 0; r < RM; r++)
#pragma unroll
                for (int c = 0; c < 4; c++) acc[r][c] = fma2(as_[r], bs_[c], acc[r][c]);
        }
        __syncthreads();
    }
#pragma unroll
    for (int r = 0; r < RM; r++) {
        int gm = mblk + ty * RM + r;
        float* crow = C0 + (size_t)gm * 128;
        float2 p0 = unpack2(acc[r][0]);
        float2 p1 = unpack2(acc[r][1]);
        float2 p2 = unpack2(acc[r][2]);
        float2 p3 = unpack2(acc[r][3]);
        float v[8] = {p0.x, p0.y, p1.x, p1.y, p2.x, p2.y, p3.x, p3.y};
#pragma unroll
        for (int c = 0; c < 4; c++) {
            v[c] = v[c] + biasC[tx * 4 + c];
            v[c] = v[c] > 0.f ? v[c] : 0.f;
            v[c + 4] = v[c + 4] + biasC[64 + tx * 4 + c];
            v[c + 4] = v[c + 4] > 0.f ? v[c + 4] : 0.f;
        }
        *(float4*)&crow[tx * 4] = make_float4(v[0], v[1], v[2], v[3]);
        *(float4*)&crow[64 + tx * 4] = make_float4(v[4], v[5], v[6], v[7]);
    }
}

// ---------------- launch ------------------------------------------------------
extern "C" void kernel_launch(void* const* d_in, const int* in_sizes, int n_in,
                              void* d_out, int out_size) {
    (void)in_sizes; (void)n_in; (void)out_size;
    const float* inputs = (const float*)d_in[0];
    const int* adj = (const int*)d_in[1];
    const float* W_att = (const float*)d_in[3];
    const float* a_src = (const float*)d_in[4];
    const float* a_dst = (const float*)d_in[5];
    const float* W_out = (const float*)d_in[6];
    const float* ao_src = (const float*)d_in[7];
    const float* ao_dst = (const float*)d_in[8];
    const float* lin_w = (const float*)d_in[9];
    const float* lin_b = (const float*)d_in[10];
    const float* ln_w = (const float*)d_in[11];
    const float* ln_b = (const float*)d_in[12];

    __half *p_in16, *p_wattT, *p_h1T, *p_x1, *p_woutT, *p_linw16, *p_h2T;
    float *p_linp, *p_att2, *p_s1, *p_s2, *p_s1b, *p_s2b, *p_ln_wT;
    unsigned* p_mask;
    cudaGetSymbolAddress((void**)&p_in16, g_in16);
    cudaGetSymbolAddress((void**)&p_wattT, g_wattT);
    cudaGetSymbolAddress((void**)&p_h1T, g_h1T);
    cudaGetSymbolAddress((void**)&p_x1, g_x1);
    cudaGetSymbolAddress((void**)&p_woutT, g_woutT);
    cudaGetSymbolAddress((void**)&p_linw16, g_linw16);
    cudaGetSymbolAddress((void**)&p_h2T, g_h2T);
    cudaGetSymbolAddress((void**)&p_linp, g_linp);
    cudaGetSymbolAddress((void**)&p_att2, g_att2);
    cudaGetSymbolAddress((void**)&p_s1, g_s1);
    cudaGetSymbolAddress((void**)&p_s2, g_s2);
    cudaGetSymbolAddress((void**)&p_s1b, g_s1b);
    cudaGetSymbolAddress((void**)&p_s2b, g_s2b);
    cudaGetSymbolAddress((void**)&p_ln_wT, g_ln_wT);
    cudaGetSymbolAddress((void**)&p_mask, g_mask);

    const int AT0_SMEM = (2 * 128 * APAD + 2 * 128 * APAD) * 2 + (128 + 128 + 1024) * 4;
    const int AT1_SMEM = (2 * 32 * APAD + 2 * 128 * APAD) * 2 + (32 + 32 + 1024) * 4;
    const int TG0_SMEM = 2 * (128 + 128) * 72 * 2;   // 73728
    const int TG1_SMEM = 2 * (128 + 32) * 72 * 2;    // 46080
    const int TG2_SMEM = 2 * (32 + 128) * 72 * 2;    // 46080
    cudaFuncSetAttribute(at_k<0>, cudaFuncAttributeMaxDynamicSharedMemorySize,
                         AT0_SMEM);
    cudaFuncSetAttribute(at_k<1>, cudaFuncAttributeMaxDynamicSharedMemorySize,
                         AT1_SMEM);
    cudaFuncSetAttribute(tg_k<0>, cudaFuncAttributeMaxDynamicSharedMemorySize,
                         TG0_SMEM);
    cudaFuncSetAttribute(tg_k<1>, cudaFuncAttributeMaxDynamicSharedMemorySize,
                         TG1_SMEM);
    cudaFuncSetAttribute(tg_k<2>, cudaFuncAttributeMaxDynamicSharedMemorySize,
                         TG2_SMEM);

    mega_prep_k<<<4624, 256>>>(adj, p_mask, inputs, p_in16, W_att, p_wattT,
                               W_out, p_woutT, ln_w, p_ln_wT, lin_w,
                               p_linw16);                                    // 0
    tg_k<0><<<dim3(8, 1, 64), 256, TG0_SMEM>>>(p_wattT, p_in16, p_h1T,
                                               a_src, a_dst, p_s1, p_s2);    // 1
    at_k<0><<<dim3(8, 1, 64), 256, AT0_SMEM>>>(p_h1T, p_s1, p_s2, p_mask,
                                               p_x1);                        // 2
    tg_k<1><<<dim3(32, 1, 8), 256, TG1_SMEM>>>(p_woutT, p_x1, p_h2T,
                                               ao_src, ao_dst, p_s1b, p_s2b); // 3
    tg_k<2><<<dim3(256, 1, 1), 256, TG2_SMEM>>>(p_x1, p_linw16, p_linp,
                                                nullptr, nullptr, nullptr,
                                                nullptr);                    // 4
    at_k<1><<<dim3(32, 1, 8), 256, AT1_SMEM>>>(p_h2T, p_s1b, p_s2b, p_mask,
                                               p_att2);                      // 5
    final_k<<<128, 256>>>(p_linp, p_ln_wT, (float*)d_out, p_att2, lin_b, ln_b); // 6
}

// round 15
// speedup vs baseline: 1.0101x; 1.0101x over previous
#include <cuda_runtime.h>
#include <cuda_fp16.h>
#include <math.h>
#include <stdint.h>

#define ALPHA 0.2f
#define LOG2E 1.44269504f
#define EXPSH 11.54156036f   // 8 * log2(e)

static const int Bq = 8, Nq = 1024, Fq = 256, Oq = 128, Hq = 8;

typedef unsigned long long u64;

// ---------------- f32x2 helpers (final fp32 gemm only) -----------------------
__device__ __forceinline__ u64 fma2(u64 a, u64 b, u64 c) {
    u64 d;
    asm("fma.rn.f32x2 %0, %1, %2, %3;" : "=l"(d) : "l"(a), "l"(b), "l"(c));
    return d;
}
__device__ __forceinline__ u64 splat2(float x) {
    u64 d;
    unsigned u = __float_as_uint(x);
    asm("mov.b64 %0, {%1, %1};" : "=l"(d) : "r"(u));
    return d;
}
__device__ __forceinline__ float2 unpack2(u64 v) {
    unsigned lo, hi;
    asm("mov.b64 {%0, %1}, %2;" : "=r"(lo), "=r"(hi) : "l"(v));
    return make_float2(__uint_as_float(lo), __uint_as_float(hi));
}
__device__ __forceinline__ float ex2a(float x) {
    float y;
    asm("ex2.approx.ftz.f32 %0, %1;" : "=f"(y) : "f"(x));
    return y;
}

// ---------------- tensor-core helpers ---------------------------------------
__device__ __forceinline__ void ldsm4(unsigned* r, const void* p) {
    unsigned a = (unsigned)__cvta_generic_to_shared(p);
    asm volatile("ldmatrix.sync.aligned.m8n8.x4.shared.b16 {%0,%1,%2,%3}, [%4];"
                 : "=r"(r[0]), "=r"(r[1]), "=r"(r[2]), "=r"(r[3]) : "r"(a));
}
__device__ __forceinline__ void mma16816(float* d, const unsigned* a,
                                         const unsigned* b, const float* c) {
    asm volatile(
        "mma.sync.aligned.m16n8k16.row.col.f32.f16.f16.f32 "
        "{%0,%1,%2,%3},{%4,%5,%6,%7},{%8,%9},{%10,%11,%12,%13};"
        : "=f"(d[0]), "=f"(d[1]), "=f"(d[2]), "=f"(d[3])
        : "r"(a[0]), "r"(a[1]), "r"(a[2]), "r"(a[3]), "r"(b[0]), "r"(b[1]),
          "f"(c[0]), "f"(c[1]), "f"(c[2]), "f"(c[3]));
}
__device__ __forceinline__ void cpa16(void* smem_dst, const void* gsrc) {
    unsigned a = (unsigned)__cvta_generic_to_shared(smem_dst);
    asm volatile("cp.async.ca.shared.global [%0], [%1], 16;" :: "r"(a), "l"(gsrc));
}
__device__ __forceinline__ void cpa_commit() {
    asm volatile("cp.async.commit_group;" ::: "memory");
}
__device__ __forceinline__ void cpa_wait0() {
    asm volatile("cp.async.wait_group 0;" ::: "memory");
}

// ---------------- scratch ----------------------------------------------------
__device__ __half g_in16[(size_t)8192 * 256];
__device__ __half g_wattT[(size_t)8 * 128 * 256];
__device__ __half g_h1T[(size_t)64 * 128 * 1024];     // [z][o][j]
__device__ __half g_x1[(size_t)8192 * 1024];          // [b*N+n][h*O+o]
__device__ __half g_woutT[(size_t)128 * 1024];
__device__ __half g_linw16[(size_t)128 * 1024];
__device__ __half g_h2T[(size_t)8 * 128 * 1024];
__device__ float g_linp[(size_t)8192 * 128];
__device__ float g_att2[(size_t)8192 * 128];
__device__ float g_s1[(size_t)64 * 1024];
__device__ float g_s2[(size_t)64 * 1024];
__device__ float g_s1b[(size_t)8 * 1024];
__device__ float g_s2b[(size_t)8 * 1024];
__device__ float g_ln_wT[(size_t)128 * 128];
__device__ unsigned g_mask[(size_t)8 * 1024 * 32];    // adj bitmask, 1MB

// ---------------- prep_a: c2h(inputs) || weight prep -------------------------
__device__ __forceinline__ void t2h_body(const float* in, __half* out, int R,
                                         int C, int bx, int by, int tid,
                                         float* tbuf /*32*33*/) {
    int c0 = bx * 32, r0 = by * 32;
    int x = tid & 31, y = tid >> 5;
    for (int i = y; i < 32; i += 8)
        tbuf[i * 33 + x] = in[(size_t)(r0 + i) * C + c0 + x];
    __syncthreads();
    for (int i = y; i < 32; i += 8)
        out[(size_t)(c0 + i) * R + r0 + x] = __float2half_rn(tbuf[x * 33 + i]);
}

__global__ __launch_bounds__(256) void prep_a_k(
    const float* __restrict__ inputs, __half* __restrict__ in16,
    const float* __restrict__ W_att, __half* __restrict__ wattT,
    const float* __restrict__ W_out, __half* __restrict__ woutT,
    const float* __restrict__ ln_w, float* __restrict__ ln_wT,
    const float* __restrict__ lin_w, __half* __restrict__ linw16) {
    __shared__ float tbuf[32 * 33];
    int bid = blockIdx.x, tid = threadIdx.x;
    if (bid < 2048) {
        // c2h inputs: 2097152 floats = 524288 float4
        int i = bid * 256 + tid;
        float4 v = ((const float4*)inputs)[i];
        half2 a = __floats2half2_rn(v.x, v.y);
        half2 b = __floats2half2_rn(v.z, v.w);
        uint2 o;
        o.x = *(unsigned*)&a;
        o.y = *(unsigned*)&b;
        *(uint2*)(in16 + (size_t)i * 4) = o;
    } else {
        int pb = bid - 2048;   // 0..527
        if (pb < 256) {
            int z = pb >> 5, rem = pb & 31;
            t2h_body(W_att + (size_t)z * 256 * 128,
                     wattT + (size_t)z * 128 * 256, 256, 128, rem & 3,
                     rem >> 2, tid, tbuf);
        } else if (pb < 384) {
            int idx = pb - 256;
            t2h_body(W_out, woutT, 1024, 128, idx & 3, idx >> 2, tid, tbuf);
        } else if (pb < 400) {
            int idx = pb - 384;
            int bx = idx & 3, by = idx >> 2;
            int c0 = bx * 32, r0 = by * 32;
            int x = tid & 31, y = tid >> 5;
            for (int i = y; i < 32; i += 8)
                tbuf[i * 33 + x] = ln_w[(size_t)(r0 + i) * 128 + c0 + x];
            __syncthreads();
            for (int i = y; i < 32; i += 8)
                ln_wT[(size_t)(c0 + i) * 128 + r0 + x] = tbuf[x * 33 + i];
        } else {
            int i = (pb - 400) * 256 + tid;
            float4 v = ((const float4*)lin_w)[i];
            half2 a = __floats2half2_rn(v.x, v.y);
            half2 b = __floats2half2_rn(v.z, v.w);
            uint2 o;
            o.x = *(unsigned*)&a;
            o.y = *(unsigned*)&b;
            *(uint2*)(linw16 + (size_t)i * 4) = o;
        }
    }
}

// adj -> bitmask: 16 ints/thread (4x int4), combine 2 lanes via shuffle
__global__ void packadj_k(const int* __restrict__ adj,
                          unsigned* __restrict__ mask) {
    int t = blockIdx.x * 256 + threadIdx.x;
    int lane = threadIdx.x & 31;
    const int4* p = (const int4*)adj + (size_t)t * 4;
    int4 a = p[0], b = p[1], c = p[2], d = p[3];
    unsigned bits = (a.x > 0 ? 1u : 0u) | (a.y > 0 ? 2u : 0u) |
                    (a.z > 0 ? 4u : 0u) | (a.w > 0 ? 8u : 0u) |
                    (b.x > 0 ? 16u : 0u) | (b.y > 0 ? 32u : 0u) |
                    (b.z > 0 ? 64u : 0u) | (b.w > 0 ? 128u : 0u) |
                    (c.x > 0 ? 256u : 0u) | (c.y > 0 ? 512u : 0u) |
                    (c.z > 0 ? 1024u : 0u) | (c.w > 0 ? 2048u : 0u) |
                    (d.x > 0 ? 4096u : 0u) | (d.y > 0 ? 8192u : 0u) |
                    (d.z > 0 ? 16384u : 0u) | (d.w > 0 ? 32768u : 0u);
    unsigned r = bits << ((lane & 1) * 16);
    r |= __shfl_xor_sync(0xffffffffu, r, 1);
    if ((lane & 1) == 0) mask[t >> 1] = r;
}

// ---------------- tensor GEMM (mma.sync, cp.async double-buffered) ----------
// C = A @ Bt^T.  MODE 0: h1T (+fused s1/s2); MODE 1: h2T (+fused s1b/s2b);
// MODE 2: linp (fp32 out, no fusion)
template <int MODE>
__global__ __launch_bounds__(256) void tg_k(const __half* __restrict__ Aroot,
                                            const __half* __restrict__ Btroot,
                                            void* __restrict__ Croot,
                                            const float* __restrict__ asrc,
                                            const float* __restrict__ adst,
                                            float* __restrict__ s1g,
                                            float* __restrict__ s2g) {
    const int K = (MODE == 0) ? 256 : 1024;
    const int NIT = K / 64;
    const int TM = (MODE == 2) ? 64 : 128;
    const int TN = (MODE == 1) ? 64 : 128;
    const int MW = TM / 32;
    const int NW = 8 / MW;
    const int NSP = TN / NW;
    const int N8 = NSP / 8;
    const int PAD = 72;
    extern __shared__ __half smh[];
    __half* As = smh;                    // 2 * TM*PAD
    __half* Bs = smh + 2 * TM * PAD;     // 2 * TN*PAD
    int tid = threadIdx.x, bx = blockIdx.x, z = blockIdx.z;

    const __half* A;
    const __half* Bt;
    __half* Ch = nullptr;
    float* Cf = nullptr;
    int lda, ldb, n0 = 0, hsel = 0;
    if (MODE == 0) {
        int b = z >> 3, h = z & 7;
        hsel = h;
        A = Aroot + (size_t)h * 128 * 256;
        lda = 256;
        Bt = Btroot + (size_t)b * 1024 * 256 + (size_t)bx * 128 * 256;
        ldb = 256;
        Ch = (__half*)Croot + (size_t)z * 131072;
        n0 = bx * 128;
    } else if (MODE == 1) {
        A = Aroot;
        lda = 1024;
        Bt = Btroot + (size_t)z * 1048576 + (size_t)bx * 64 * 1024;
        ldb = 1024;
        Ch = (__half*)Croot + (size_t)z * 131072;
        n0 = bx * 64;
    } else {
        A = Aroot + (size_t)bx * 64 * 1024;
        lda = 1024;
        Bt = Btroot;
        ldb = 1024;
        Cf = (float*)Croot + (size_t)bx * 64 * 128;
    }

    int w = tid >> 5, lane = tid & 31;
    int mw = w % MW, nw = w / MW;
    int wm = mw * 32, wn = nw * NSP;
    int ar = (lane & 7) | (((lane >> 3) & 1) << 3);
    int akh = (lane >> 4) << 3;
    int bn = ((lane >> 4) << 3) | (lane & 7);
    int bkh = ((lane >> 3) & 1) << 3;

    auto loadTiles = [&](int buf, int k0) {
        __half* ab = As + buf * TM * PAD;
        __half* bb = Bs + buf * TN * PAD;
#pragma unroll
        for (int q = 0; q < TM / 32; q++) {
            int f = tid + q * 256;
            int row = f >> 3, c8 = f & 7;
            cpa16(&ab[row * PAD + c8 * 8], A + (size_t)row * lda + k0 + c8 * 8);
        }
#pragma unroll
        for (int q = 0; q < TN / 32; q++) {
            int f = tid + q * 256;
            int row = f >> 3, c8 = f & 7;
            cpa16(&bb[row * PAD + c8 * 8], Bt + (size_t)row * ldb + k0 + c8 * 8);
        }
        cpa_commit();
    };

    float acc[2][N8][4];
#pragma unroll
    for (int mt = 0; mt < 2; mt++)
#pragma unroll
        for (int n8 = 0; n8 < N8; n8++)
#pragma unroll
            for (int e = 0; e < 4; e++) acc[mt][n8][e] = 0.f;

    loadTiles(0, 0);
    for (int it = 0; it < NIT; it++) {
        int cb = it & 1;
        cpa_wait0();
        __syncthreads();
        if (it + 1 < NIT) loadTiles(cb ^ 1, (it + 1) * 64);
        const __half* ab = As + cb * TM * PAD;
        const __half* bb = Bs + cb * TN * PAD;
#pragma unroll
        for (int kk = 0; kk < 64; kk += 16) {
            unsigned af[2][4], bf[N8 / 2][4];
            ldsm4(af[0], &ab[(wm + ar) * PAD + kk + akh]);
            ldsm4(af[1], &ab[(wm + 16 + ar) * PAD + kk + akh]);
#pragma unroll
            for (int np = 0; np < N8 / 2; np++)
                ldsm4(bf[np], &bb[(wn + np * 16 + bn) * PAD + kk + bkh]);
#pragma unroll
            for (int mt = 0; mt < 2; mt++)
#pragma unroll
                for (int n8 = 0; n8 < N8; n8++)
                    mma16816(acc[mt][n8], af[mt], &bf[n8 >> 1][(n8 & 1) * 2],
                             acc[mt][n8]);
        }
    }

    __syncthreads();
    int r0 = lane >> 2, cc = (lane & 3) * 2;

    // C stores
#pragma unroll
    for (int mt = 0; mt < 2; mt++)
#pragma unroll
        for (int n8 = 0; n8 < N8; n8++) {
            int row0 = wm + mt * 16 + r0;
            int col = wn + n8 * 8 + cc;
            if (MODE <= 1) {
                half2 lo = __floats2half2_rn(acc[mt][n8][0], acc[mt][n8][1]);
                half2 hi = __floats2half2_rn(acc[mt][n8][2], acc[mt][n8][3]);
                *(half2*)&Ch[(size_t)row0 * 1024 + n0 + col] = lo;
                *(half2*)&Ch[(size_t)(row0 + 8) * 1024 + n0 + col] = hi;
            } else {
                *(float2*)&Cf[(size_t)row0 * 128 + col] =
                    make_float2(acc[mt][n8][0], acc[mt][n8][1]);
                *(float2*)&Cf[(size_t)(row0 + 8) * 128 + col] =
                    make_float2(acc[mt][n8][2], acc[mt][n8][3]);
            }
        }

    // fused s1/s2 (MODE<=1): s[j] = LOG2E * sum_o a[o] * h[o][j]
    if (MODE <= 1) {
        float a1r[4], a2r[4];
        int rws[4] = {wm + r0, wm + r0 + 8, wm + 16 + r0, wm + 24 + r0};
#pragma unroll
        for (int q = 0; q < 4; q++) {
            a1r[q] = asrc[hsel * 128 + rws[q]] * LOG2E;
            a2r[q] = adst[hsel * 128 + rws[q]] * LOG2E;
        }
        float* red = (float*)smh;   // reuse smem
#pragma unroll
        for (int n8 = 0; n8 < N8; n8++) {
            float s1lo = a1r[0] * acc[0][n8][0] + a1r[1] * acc[0][n8][2] +
                         a1r[2] * acc[1][n8][0] + a1r[3] * acc[1][n8][2];
            float s1hi = a1r[0] * acc[0][n8][1] + a1r[1] * acc[0][n8][3] +
                         a1r[2] * acc[1][n8][1] + a1r[3] * acc[1][n8][3];
            float s2lo = a2r[0] * acc[0][n8][0] + a2r[1] * acc[0][n8][2] +
                         a2r[2] * acc[1][n8][0] + a2r[3] * acc[1][n8][2];
            float s2hi = a2r[0] * acc[0][n8][1] + a2r[1] * acc[0][n8][3] +
                         a2r[2] * acc[1][n8][1] + a2r[3] * acc[1][n8][3];
#pragma unroll
            for (int o = 4; o < 32; o <<= 1) {
                s1lo += __shfl_xor_sync(0xffffffffu, s1lo, o);
                s1hi += __shfl_xor_sync(0xffffffffu, s1hi, o);
                s2lo += __shfl_xor_sync(0xffffffffu, s2lo, o);
                s2hi += __shfl_xor_sync(0xffffffffu, s2hi, o);
            }
            if (lane < 4) {
                int col = wn + n8 * 8 + lane * 2;
                red[(mw * TN + col) * 2 + 0] = s1lo;
                red[(mw * TN + col) * 2 + 1] = s2lo;
                red[(mw * TN + col + 1) * 2 + 0] = s1hi;
                red[(mw * TN + col + 1) * 2 + 1] = s2hi;
            }
        }
        __syncthreads();
        if (tid < TN) {
            float s1 = 0.f, s2 = 0.f;
#pragma unroll
            for (int m = 0; m < MW; m++) {
                s1 += red[(m * TN + tid) * 2 + 0];
                s2 += red[(m * TN + tid) * 2 + 1];
            }
            s1g[(size_t)z * 1024 + n0 + tid] = s1;
            s2g[(size_t)z * 1024 + n0 + tid] = s2;
        }
    }
}

// ---------------- pipelined HMMA fused attention ------------------------------
// scores pre-scaled by log2e: p = bit ? ex2(lrelu(s1+s2) - 8*log2e) : 0
#define APAD 72
template <int MODE>
__global__ __launch_bounds__(256) void at_k(const __half* __restrict__ hT,
                                            const float* __restrict__ s1g,
                                            const float* __restrict__ s2g,
                                            const unsigned* __restrict__ mask,
                                            void* __restrict__ outp) {
    const int TM = (MODE == 0) ? 128 : 64;
    const int MW = TM / 32;
    const int NW = 8 / MW;
    const int NSP = 128 / NW;
    const int N8 = NSP / 8;
    const int SC = TM / 8;
    const int LOGSC = (MODE == 0) ? 4 : 3;

    extern __shared__ char smraw[];
    __half* Ps = (__half*)smraw;
    __half* Vs = Ps + 2 * TM * APAD;
    float* s1s = (float*)(Vs + 2 * 128 * APAD);
    float* ds = s1s + TM;
    float* s2s = ds + TM;

    int tid = threadIdx.x, bx = blockIdx.x, z = blockIdx.z;
    int b, h;
    if (MODE == 0) { b = z >> 3; h = z & 7; }
    else { b = z; h = 0; }
    int i0 = bx * TM;
    const __half* hz = hT + (size_t)z * 131072;
    const unsigned* maskb = mask + (size_t)b * 32768;

    ((float4*)s2s)[tid] = ((const float4*)(s2g + (size_t)z * 1024))[tid];
    if (tid < TM) s1s[tid] = s1g[(size_t)z * 1024 + i0 + tid];
    __syncthreads();

    int w = tid >> 5, lane = tid & 31;
    int mw = w % MW, nw = w / MW;
    int wm = mw * 32, wn = nw * NSP;
    int ar = (lane & 7) | (((lane >> 3) & 1) << 3);
    int akh = (lane >> 4) << 3;
    int bn = ((lane >> 4) << 3) | (lane & 7);
    int bkh = ((lane >> 3) & 1) << 3;

    float acc[2][N8][4];
#pragma unroll
    for (int mt = 0; mt < 2; mt++)
#pragma unroll
        for (int n8 = 0; n8 < N8; n8++)
#pragma unroll
            for (int e = 0; e < 4; e++) acc[mt][n8][e] = 0.f;
    float dl[SC];
#pragma unroll
    for (int s = 0; s < SC; s++) dl[s] = 0.f;

    int bitpos = (2 * lane) & 31;

    auto issueV = [&](int buf, int j0) {
        __half* vb = Vs + buf * 128 * APAD;
#pragma unroll
        for (int q = 0; q < 4; q++) {
            int f = tid + q * 256;
            int row = f >> 3, c8 = f & 7;
            cpa16(&vb[row * APAD + c8 * 8],
                  hz + (size_t)row * 1024 + j0 + c8 * 8);
        }
        cpa_commit();
    };
    auto loadMaskW = [&](int j0) -> unsigned {
        int s = lane & (SC - 1);
        int wsel = (lane >> LOGSC) & 1;
        return maskb[((size_t)(i0 + w + s * 8) << 5) + (j0 >> 5) + wsel];
    };
    auto buildP = [&](int buf, int j0, unsigned mpre) {
        __half* pb = Ps + buf * TM * APAD;
        float s2a = s2s[j0 + 2 * lane];
        float s2b = s2s[j0 + 2 * lane + 1];
#pragma unroll
        for (int s = 0; s < SC; s++) {
            int i = w + s * 8;
            unsigned m = __shfl_sync(0xffffffffu, mpre, ((lane >> 4) << LOGSC) | s);
            unsigned two = (m >> bitpos) & 3u;
            float s1v = s1s[i];
            float e1 = s1v + s2a;
            e1 = e1 > 0.f ? e1 : ALPHA * e1;
            float e2 = s1v + s2b;
            e2 = e2 > 0.f ? e2 : ALPHA * e2;
            float p1 = (two & 1u) ? ex2a(e1 - EXPSH) : 0.f;
            float p2 = (two & 2u) ? ex2a(e2 - EXPSH) : 0.f;
            *(half2*)&pb[i * APAD + 2 * lane] = __floats2half2_rn(p1, p2);
            dl[s] += p1 + p2;
        }
    };

    unsigned mpre = loadMaskW(0);
    issueV(0, 0);
    buildP(0, 0, mpre);

    for (int t = 0; t < 16; t++) {
        int cb = t & 1, nb = cb ^ 1;
        cpa_wait0();
        __syncthreads();
        if (t < 15) {
            issueV(nb, (t + 1) * 64);
            mpre = loadMaskW((t + 1) * 64);
        }
        const __half* pb = Ps + cb * TM * APAD;
        const __half* vb = Vs + cb * 128 * APAD;
#pragma unroll
        for (int kk = 0; kk < 64; kk += 16) {
            unsigned af[2][4], bf[N8 / 2][4];
            ldsm4(af[0], &pb[(wm + ar) * APAD + kk + akh]);
            ldsm4(af[1], &pb[(wm + 16 + ar) * APAD + kk + akh]);
#pragma unroll
            for (int np = 0; np < N8 / 2; np++)
                ldsm4(bf[np], &vb[(wn + np * 16 + bn) * APAD + kk + bkh]);
#pragma unroll
            for (int mt = 0; mt < 2; mt++)
#pragma unroll
                for (int n8 = 0; n8 < N8; n8++)
                    mma16816(acc[mt][n8], af[mt], &bf[n8 >> 1][(n8 & 1) * 2],
                             acc[mt][n8]);
        }
        if (t < 15) buildP(nb, (t + 1) * 64, mpre);
    }

#pragma unroll
    for (int s = 0; s < SC; s++) {
        float v = dl[s];
#pragma unroll
        for (int o = 16; o; o >>= 1) v += __shfl_xor_sync(0xffffffffu, v, o);
        if (lane == 0) ds[s * 8 + w] = v;
    }
    __syncthreads();

    int r0 = lane >> 2, cc = (lane & 3) * 2;
#pragma unroll
    for (int mt = 0; mt < 2; mt++)
#pragma unroll
        for (int n8 = 0; n8 < N8; n8++) {
            int row0 = wm + mt * 16 + r0, row1 = row0 + 8;
            int col = wn + n8 * 8 + cc;
            float inv0 = 1.f / ds[row0], inv1 = 1.f / ds[row1];
            float f0 = acc[mt][n8][0] * inv0, f1 = acc[mt][n8][1] * inv0;
            float f2 = acc[mt][n8][2] * inv1, f3 = acc[mt][n8][3] * inv1;
            if (MODE == 0) {
                f0 = f0 > 0.f ? f0 : expm1f(f0);
                f1 = f1 > 0.f ? f1 : expm1f(f1);
                f2 = f2 > 0.f ? f2 : expm1f(f2);
                f3 = f3 > 0.f ? f3 : expm1f(f3);
                __half* x1 = (__half*)outp;
                *(half2*)&x1[((size_t)b * 1024 + i0 + row0) * 1024 + h * 128 + col] =
                    __floats2half2_rn(f0, f1);
                *(half2*)&x1[((size_t)b * 1024 + i0 + row1) * 1024 + h * 128 + col] =
                    __floats2half2_rn(f2, f3);
            } else {
                float* o2 = (float*)outp;
                *(float2*)&o2[((size_t)b * 1024 + i0 + row0) * 128 + col] =
                    make_float2(f0, f1);
                *(float2*)&o2[((size_t)b * 1024 + i0 + row1) * 128 + col] =
                    make_float2(f2, f3);
            }
        }
}

// ---------------- final fp32 gemm: relu((linp+att2+lin_b) @ ln_wT + ln_b) ----
__global__ void __launch_bounds__(256)
final_k(const float* __restrict__ A0, const float* __restrict__ B0,
        float* __restrict__ C0, const float* __restrict__ add,
        const float* __restrict__ biasA, const float* __restrict__ biasC) {
    const int BK = 32, BM = 64, RM = 4;
    __shared__ float As[BK][BM + 4];
    __shared__ float Bs[BK][128 + 4];
    int mblk = blockIdx.x * BM;
    int tid = threadIdx.x;
    int tx = tid % 16, ty = tid / 16;
    u64 acc[RM][4];
#pragma unroll
    for (int r = 0; r < RM; r++)
#pragma unroll
        for (int c = 0; c < 4; c++) acc[r][c] = 0ull;

    for (int k0 = 0; k0 < 128; k0 += BK) {
#pragma unroll
        for (int q = 0; q < BM / 32; q++) {
            int f = tid + q * 256;
            int m = f >> 3;
            int kk = (f & 7) * 4;
            const float* ap = A0 + (size_t)(mblk + m) * 128 + (k0 + kk);
            const float* dp = add + (size_t)(mblk + m) * 128 + (k0 + kk);
            const float* bp = biasA + (k0 + kk);
            float4 v;
            v.x = ap[0] + dp[0] + bp[0];
            v.y = ap[1] + dp[1] + bp[1];
            v.z = ap[2] + dp[2] + bp[2];
            v.w = ap[3] + dp[3] + bp[3];
            As[kk + 0][m] = v.x;
            As[kk + 1][m] = v.y;
            As[kk + 2][m] = v.z;
            As[kk + 3][m] = v.w;
        }
#pragma unroll
        for (int q = 0; q < 4; q++) {
            int f = tid + q * 256;
            int kk = f >> 5;
            int nn = (f & 31) * 4;
            *(float4*)&Bs[kk][nn] = *(const float4*)(B0 + (size_t)(k0 + kk) * 128 + nn);
        }
        __syncthreads();
#pragma unroll 8
        for (int kk = 0; kk < BK; kk++) {
            u64 as_[RM];
            float4 av = *(const float4*)&As[kk][ty * RM];
            as_[0] = splat2(av.x);
            as_[1] = splat2(av.y);
            as_[2] = splat2(av.z);
            as_[3] = splat2(av.w);
            ulonglong2 b0 = *(const ulonglong2*)&Bs[kk][tx * 4];
            ulonglong2 b1 = *(const ulonglong2*)&Bs[kk][64 + tx * 4];
            u64 bs_[4] = {b0.x, b0.y, b1.x, b1.y};
#pragma unroll
            for (int r = 0; r < RM; r++)
#pragma unroll
                for (int c = 0; c < 4; c++) acc[r][c] = fma2(as_[r], bs_[c], acc[r][c]);
        }
        __syncthreads();
    }
#pragma unroll
    for (int r = 0; r < RM; r++) {
        int gm = mblk + ty * RM + r;
        float* crow = C0 + (size_t)gm * 128;
        float2 p0 = unpack2(acc[r][0]);
        float2 p1 = unpack2(acc[r][1]);
        float2 p2 = unpack2(acc[r][2]);
        float2 p3 = unpack2(acc[r][3]);
        float v[8] = {p0.x, p0.y, p1.x, p1.y, p2.x, p2.y, p3.x, p3.y};
#pragma unroll
        for (int c = 0; c < 4; c++) {
            v[c] = v[c] + biasC[tx * 4 + c];
            v[c] = v[c] > 0.f ? v[c] : 0.f;
            v[c + 4] = v[c + 4] + biasC[64 + tx * 4 + c];
            v[c + 4] = v[c + 4] > 0.f ? v[c + 4] : 0.f;
        }
        *(float4*)&crow[tx * 4] = make_float4(v[0], v[1], v[2], v[3]);
        *(float4*)&crow[64 + tx * 4] = make_float4(v[4], v[5], v[6], v[7]);
    }
}

// ---------------- launch ------------------------------------------------------
extern "C" void kernel_launch(void* const* d_in, const int* in_sizes, int n_in,
                              void* d_out, int out_size) {
    (void)in_sizes; (void)n_in; (void)out_size;
    const float* inputs = (const float*)d_in[0];
    const int* adj = (const int*)d_in[1];
    const float* W_att = (const float*)d_in[3];
    const float* a_src = (const float*)d_in[4];
    const float* a_dst = (const float*)d_in[5];
    const float* W_out = (const float*)d_in[6];
    const float* ao_src = (const float*)d_in[7];
    const float* ao_dst = (const float*)d_in[8];
    const float* lin_w = (const float*)d_in[9];
    const float* lin_b = (const float*)d_in[10];
    const float* ln_w = (const float*)d_in[11];
    const float* ln_b = (const float*)d_in[12];

    __half *p_in16, *p_wattT, *p_h1T, *p_x1, *p_woutT, *p_linw16, *p_h2T;
    float *p_linp, *p_att2, *p_s1, *p_s2, *p_s1b, *p_s2b, *p_ln_wT;
    unsigned* p_mask;
    cudaGetSymbolAddress((void**)&p_in16, g_in16);
    cudaGetSymbolAddress((void**)&p_wattT, g_wattT);
    cudaGetSymbolAddress((void**)&p_h1T, g_h1T);
    cudaGetSymbolAddress((void**)&p_x1, g_x1);
    cudaGetSymbolAddress((void**)&p_woutT, g_woutT);
    cudaGetSymbolAddress((void**)&p_linw16, g_linw16);
    cudaGetSymbolAddress((void**)&p_h2T, g_h2T);
    cudaGetSymbolAddress((void**)&p_linp, g_linp);
    cudaGetSymbolAddress((void**)&p_att2, g_att2);
    cudaGetSymbolAddress((void**)&p_s1, g_s1);
    cudaGetSymbolAddress((void**)&p_s2, g_s2);
    cudaGetSymbolAddress((void**)&p_s1b, g_s1b);
    cudaGetSymbolAddress((void**)&p_s2b, g_s2b);
    cudaGetSymbolAddress((void**)&p_ln_wT, g_ln_wT);
    cudaGetSymbolAddress((void**)&p_mask, g_mask);

    const int AT0_SMEM = (2 * 128 * APAD + 2 * 128 * APAD) * 2 + (128 + 128 + 1024) * 4;
    const int AT1_SMEM = (2 * 64 * APAD + 2 * 128 * APAD) * 2 + (64 + 64 + 1024) * 4;
    const int TG0_SMEM = 2 * (128 + 128) * 72 * 2;   // 73728
    const int TG1_SMEM = 2 * (128 + 64) * 72 * 2;    // 55296
    const int TG2_SMEM = 2 * (64 + 128) * 72 * 2;    // 55296
    cudaFuncSetAttribute(at_k<0>, cudaFuncAttributeMaxDynamicSharedMemorySize,
                         AT0_SMEM);
    cudaFuncSetAttribute(at_k<1>, cudaFuncAttributeMaxDynamicSharedMemorySize,
                         AT1_SMEM);
    cudaFuncSetAttribute(tg_k<0>, cudaFuncAttributeMaxDynamicSharedMemorySize,
                         TG0_SMEM);
    cudaFuncSetAttribute(tg_k<1>, cudaFuncAttributeMaxDynamicSharedMemorySize,
                         TG1_SMEM);
    cudaFuncSetAttribute(tg_k<2>, cudaFuncAttributeMaxDynamicSharedMemorySize,
                         TG2_SMEM);

    // order: packadj moved after tg0 so at_k<0> lands in ncu's capture slot
    prep_a_k<<<2576, 256>>>(inputs, p_in16, W_att, p_wattT, W_out, p_woutT,
                            ln_w, p_ln_wT, lin_w, p_linw16);                 // 0
    tg_k<0><<<dim3(8, 1, 64), 256, TG0_SMEM>>>(p_wattT, p_in16, p_h1T,
                                               a_src, a_dst, p_s1, p_s2);    // 1
    packadj_k<<<2048, 256>>>(adj, p_mask);                                   // 2
    at_k<0><<<dim3(8, 1, 64), 256, AT0_SMEM>>>(p_h1T, p_s1, p_s2, p_mask,
                                               p_x1);                        // 3
    tg_k<1><<<dim3(16, 1, 8), 256, TG1_SMEM>>>(p_woutT, p_x1, p_h2T,
                                               ao_src, ao_dst, p_s1b, p_s2b); // 4
    tg_k<2><<<dim3(128, 1, 1), 256, TG2_SMEM>>>(p_x1, p_linw16, p_linp,
                                                nullptr, nullptr, nullptr,
                                                nullptr);                    // 5
    at_k<1><<<dim3(16, 1, 8), 256, AT1_SMEM>>>(p_h2T, p_s1b, p_s2b, p_mask,
                                               p_att2);                      // 6
    final_k<<<128, 256>>>(p_linp, p_ln_wT, (float*)d_out, p_att2, lin_b, ln_b); // 7
}

// round 16
// speedup vs baseline: 1.0956x; 1.0846x over previous
#include <cuda_runtime.h>
#include <cuda_fp16.h>
#include <math.h>
#include <stdint.h>

#define ALPHA 0.2f
#define LOG2E 1.44269504f
#define EXPSH 11.54156036f   // 8 * log2(e)

static const int Bq = 8, Nq = 1024, Fq = 256, Oq = 128, Hq = 8;

typedef unsigned long long u64;

// ---------------- f32x2 helpers (final fp32 gemm only) -----------------------
__device__ __forceinline__ u64 fma2(u64 a, u64 b, u64 c) {
    u64 d;
    asm("fma.rn.f32x2 %0, %1, %2, %3;" : "=l"(d) : "l"(a), "l"(b), "l"(c));
    return d;
}
__device__ __forceinline__ u64 splat2(float x) {
    u64 d;
    unsigned u = __float_as_uint(x);
    asm("mov.b64 %0, {%1, %1};" : "=l"(d) : "r"(u));
    return d;
}
__device__ __forceinline__ float2 unpack2(u64 v) {
    unsigned lo, hi;
    asm("mov.b64 {%0, %1}, %2;" : "=r"(lo), "=r"(hi) : "l"(v));
    return make_float2(__uint_as_float(lo), __uint_as_float(hi));
}
__device__ __forceinline__ float ex2a(float x) {
    float y;
    asm("ex2.approx.ftz.f32 %0, %1;" : "=f"(y) : "f"(x));
    return y;
}

// ---------------- tensor-core helpers ---------------------------------------
__device__ __forceinline__ void ldsm4(unsigned* r, const void* p) {
    unsigned a = (unsigned)__cvta_generic_to_shared(p);
    asm volatile("ldmatrix.sync.aligned.m8n8.x4.shared.b16 {%0,%1,%2,%3}, [%4];"
                 : "=r"(r[0]), "=r"(r[1]), "=r"(r[2]), "=r"(r[3]) : "r"(a));
}
__device__ __forceinline__ void mma16816(float* d, const unsigned* a,
                                         const unsigned* b, const float* c) {
    asm volatile(
        "mma.sync.aligned.m16n8k16.row.col.f32.f16.f16.f32 "
        "{%0,%1,%2,%3},{%4,%5,%6,%7},{%8,%9},{%10,%11,%12,%13};"
        : "=f"(d[0]), "=f"(d[1]), "=f"(d[2]), "=f"(d[3])
        : "r"(a[0]), "r"(a[1]), "r"(a[2]), "r"(a[3]), "r"(b[0]), "r"(b[1]),
          "f"(c[0]), "f"(c[1]), "f"(c[2]), "f"(c[3]));
}
__device__ __forceinline__ void cpa16(void* smem_dst, const void* gsrc) {
    unsigned a = (unsigned)__cvta_generic_to_shared(smem_dst);
    asm volatile("cp.async.ca.shared.global [%0], [%1], 16;" :: "r"(a), "l"(gsrc));
}
__device__ __forceinline__ void cpa_commit() {
    asm volatile("cp.async.commit_group;" ::: "memory");
}
__device__ __forceinline__ void cpa_wait0() {
    asm volatile("cp.async.wait_group 0;" ::: "memory");
}

// ---------------- scratch ----------------------------------------------------
__device__ __half g_in16[(size_t)8192 * 256];
__device__ __half g_wattT[(size_t)8 * 128 * 256];
__device__ __half g_h1T[(size_t)64 * 128 * 1024];     // [z][o][j]
__device__ __half g_x1[(size_t)8192 * 1024];          // [b*N+n][h*O+o]
__device__ __half g_woutT[(size_t)128 * 1024];
__device__ __half g_linw16[(size_t)128 * 1024];
__device__ __half g_h2T[(size_t)8 * 128 * 1024];
__device__ float g_linp[(size_t)8192 * 128];
__device__ float g_att2[(size_t)8192 * 128];
__device__ float g_s1[(size_t)64 * 1024];
__device__ float g_s2[(size_t)64 * 1024];
__device__ float g_s1b[(size_t)8 * 1024];
__device__ float g_s2b[(size_t)8 * 1024];
__device__ float g_ln_wT[(size_t)128 * 128];
__device__ unsigned g_mask[(size_t)8 * 8 * 8 * 512];  // maskP, 1MB

// ---------------- prep_a: c2h(inputs) || weight prep -------------------------
__device__ __forceinline__ void t2h_body(const float* in, __half* out, int R,
                                         int C, int bx, int by, int tid,
                                         float* tbuf /*32*33*/) {
    int c0 = bx * 32, r0 = by * 32;
    int x = tid & 31, y = tid >> 5;
    for (int i = y; i < 32; i += 8)
        tbuf[i * 33 + x] = in[(size_t)(r0 + i) * C + c0 + x];
    __syncthreads();
    for (int i = y; i < 32; i += 8)
        out[(size_t)(c0 + i) * R + r0 + x] = __float2half_rn(tbuf[x * 33 + i]);
}

__global__ __launch_bounds__(256) void prep_a_k(
    const float* __restrict__ inputs, __half* __restrict__ in16,
    const float* __restrict__ W_att, __half* __restrict__ wattT,
    const float* __restrict__ W_out, __half* __restrict__ woutT,
    const float* __restrict__ ln_w, float* __restrict__ ln_wT,
    const float* __restrict__ lin_w, __half* __restrict__ linw16) {
    __shared__ float tbuf[32 * 33];
    int bid = blockIdx.x, tid = threadIdx.x;
    if (bid < 2048) {
        int i = bid * 256 + tid;
        float4 v = ((const float4*)inputs)[i];
        half2 a = __floats2half2_rn(v.x, v.y);
        half2 b = __floats2half2_rn(v.z, v.w);
        uint2 o;
        o.x = *(unsigned*)&a;
        o.y = *(unsigned*)&b;
        *(uint2*)(in16 + (size_t)i * 4) = o;
    } else {
        int pb = bid - 2048;   // 0..527
        if (pb < 256) {
            int z = pb >> 5, rem = pb & 31;
            t2h_body(W_att + (size_t)z * 256 * 128,
                     wattT + (size_t)z * 128 * 256, 256, 128, rem & 3,
                     rem >> 2, tid, tbuf);
        } else if (pb < 384) {
            int idx = pb - 256;
            t2h_body(W_out, woutT, 1024, 128, idx & 3, idx >> 2, tid, tbuf);
        } else if (pb < 400) {
            int idx = pb - 384;
            int bx = idx & 3, by = idx >> 2;
            int c0 = bx * 32, r0 = by * 32;
            int x = tid & 31, y = tid >> 5;
            for (int i = y; i < 32; i += 8)
                tbuf[i * 33 + x] = ln_w[(size_t)(r0 + i) * 128 + c0 + x];
            __syncthreads();
            for (int i = y; i < 32; i += 8)
                ln_wT[(size_t)(c0 + i) * 128 + r0 + x] = tbuf[x * 33 + i];
        } else {
            int i = (pb - 400) * 256 + tid;
            float4 v = ((const float4*)lin_w)[i];
            half2 a = __floats2half2_rn(v.x, v.y);
            half2 b = __floats2half2_rn(v.z, v.w);
            uint2 o;
            o.x = *(unsigned*)&a;
            o.y = *(unsigned*)&b;
            *(uint2*)(linw16 + (size_t)i * 4) = o;
        }
    }
}

// adj -> strided-row mask: maskP[((b*8+ib)*8+w)*512 + jp]
//   bit (2s+e) = adj[b][ib*128 + w + 8s][2*jp + e] > 0,  s=0..15, e=0..1
__global__ void packadj_k(const int* __restrict__ adj,
                          unsigned* __restrict__ maskP) {
    int widx = blockIdx.x * 256 + threadIdx.x;    // 0..262143
    int jp = widx & 511;
    int w = (widx >> 9) & 7;
    int ib = (widx >> 12) & 7;
    int b = widx >> 15;
    const int* base = adj + ((size_t)b * 1024 + ib * 128 + w) * 1024 + 2 * jp;
    int2 v[16];
#pragma unroll
    for (int s = 0; s < 16; s++)
        v[s] = *(const int2*)(base + (size_t)s * 8 * 1024);
    unsigned bits = 0;
#pragma unroll
    for (int s = 0; s < 16; s++) {
        bits |= (v[s].x > 0 ? 1u : 0u) << (2 * s);
        bits |= (v[s].y > 0 ? 2u : 0u) << (2 * s);
    }
    maskP[widx] = bits;
}

// ---------------- tensor GEMM (mma.sync, cp.async double-buffered) ----------
// C = A @ Bt^T.  MODE 0: h1T (+fused s1/s2); MODE 1: h2T (+fused s1b/s2b);
// MODE 2: linp (fp32 out, no fusion)
template <int MODE>
__global__ __launch_bounds__(256) void tg_k(const __half* __restrict__ Aroot,
                                            const __half* __restrict__ Btroot,
                                            void* __restrict__ Croot,
                                            const float* __restrict__ asrc,
                                            const float* __restrict__ adst,
                                            float* __restrict__ s1g,
                                            float* __restrict__ s2g) {
    const int K = (MODE == 0) ? 256 : 1024;
    const int NIT = K / 64;
    const int TM = (MODE == 2) ? 64 : 128;
    const int TN = (MODE == 1) ? 64 : 128;
    const int MW = TM / 32;
    const int NW = 8 / MW;
    const int NSP = TN / NW;
    const int N8 = NSP / 8;
    const int PAD = 72;
    extern __shared__ __half smh[];
    __half* As = smh;                    // 2 * TM*PAD
    __half* Bs = smh + 2 * TM * PAD;     // 2 * TN*PAD
    int tid = threadIdx.x, bx = blockIdx.x, z = blockIdx.z;

    const __half* A;
    const __half* Bt;
    __half* Ch = nullptr;
    float* Cf = nullptr;
    int lda, ldb, n0 = 0, hsel = 0;
    if (MODE == 0) {
        int b = z >> 3, h = z & 7;
        hsel = h;
        A = Aroot + (size_t)h * 128 * 256;
        lda = 256;
        Bt = Btroot + (size_t)b * 1024 * 256 + (size_t)bx * 128 * 256;
        ldb = 256;
        Ch = (__half*)Croot + (size_t)z * 131072;
        n0 = bx * 128;
    } else if (MODE == 1) {
        A = Aroot;
        lda = 1024;
        Bt = Btroot + (size_t)z * 1048576 + (size_t)bx * 64 * 1024;
        ldb = 1024;
        Ch = (__half*)Croot + (size_t)z * 131072;
        n0 = bx * 64;
    } else {
        A = Aroot + (size_t)bx * 64 * 1024;
        lda = 1024;
        Bt = Btroot;
        ldb = 1024;
        Cf = (float*)Croot + (size_t)bx * 64 * 128;
    }

    int w = tid >> 5, lane = tid & 31;
    int mw = w % MW, nw = w / MW;
    int wm = mw * 32, wn = nw * NSP;
    int ar = (lane & 7) | (((lane >> 3) & 1) << 3);
    int akh = (lane >> 4) << 3;
    int bn = ((lane >> 4) << 3) | (lane & 7);
    int bkh = ((lane >> 3) & 1) << 3;

    auto loadTiles = [&](int buf, int k0) {
        __half* ab = As + buf * TM * PAD;
        __half* bb = Bs + buf * TN * PAD;
#pragma unroll
        for (int q = 0; q < TM / 32; q++) {
            int f = tid + q * 256;
            int row = f >> 3, c8 = f & 7;
            cpa16(&ab[row * PAD + c8 * 8], A + (size_t)row * lda + k0 + c8 * 8);
        }
#pragma unroll
        for (int q = 0; q < TN / 32; q++) {
            int f = tid + q * 256;
            int row = f >> 3, c8 = f & 7;
            cpa16(&bb[row * PAD + c8 * 8], Bt + (size_t)row * ldb + k0 + c8 * 8);
        }
        cpa_commit();
    };

    float acc[2][N8][4];
#pragma unroll
    for (int mt = 0; mt < 2; mt++)
#pragma unroll
        for (int n8 = 0; n8 < N8; n8++)
#pragma unroll
            for (int e = 0; e < 4; e++) acc[mt][n8][e] = 0.f;

    loadTiles(0, 0);
    for (int it = 0; it < NIT; it++) {
        int cb = it & 1;
        cpa_wait0();
        __syncthreads();
        if (it + 1 < NIT) loadTiles(cb ^ 1, (it + 1) * 64);
        const __half* ab = As + cb * TM * PAD;
        const __half* bb = Bs + cb * TN * PAD;
#pragma unroll
        for (int kk = 0; kk < 64; kk += 16) {
            unsigned af[2][4], bf[N8 / 2][4];
            ldsm4(af[0], &ab[(wm + ar) * PAD + kk + akh]);
            ldsm4(af[1], &ab[(wm + 16 + ar) * PAD + kk + akh]);
#pragma unroll
            for (int np = 0; np < N8 / 2; np++)
                ldsm4(bf[np], &bb[(wn + np * 16 + bn) * PAD + kk + bkh]);
#pragma unroll
            for (int mt = 0; mt < 2; mt++)
#pragma unroll
                for (int n8 = 0; n8 < N8; n8++)
                    mma16816(acc[mt][n8], af[mt], &bf[n8 >> 1][(n8 & 1) * 2],
                             acc[mt][n8]);
        }
    }

    __syncthreads();
    int r0 = lane >> 2, cc = (lane & 3) * 2;

    // C stores
#pragma unroll
    for (int mt = 0; mt < 2; mt++)
#pragma unroll
        for (int n8 = 0; n8 < N8; n8++) {
            int row0 = wm + mt * 16 + r0;
            int col = wn + n8 * 8 + cc;
            if (MODE <= 1) {
                half2 lo = __floats2half2_rn(acc[mt][n8][0], acc[mt][n8][1]);
                half2 hi = __floats2half2_rn(acc[mt][n8][2], acc[mt][n8][3]);
                *(half2*)&Ch[(size_t)row0 * 1024 + n0 + col] = lo;
                *(half2*)&Ch[(size_t)(row0 + 8) * 1024 + n0 + col] = hi;
            } else {
                *(float2*)&Cf[(size_t)row0 * 128 + col] =
                    make_float2(acc[mt][n8][0], acc[mt][n8][1]);
                *(float2*)&Cf[(size_t)(row0 + 8) * 128 + col] =
                    make_float2(acc[mt][n8][2], acc[mt][n8][3]);
            }
        }

    // fused s1/s2 (MODE<=1): s[j] = LOG2E * sum_o a[o] * h[o][j]
    if (MODE <= 1) {
        float a1r[4], a2r[4];
        int rws[4] = {wm + r0, wm + r0 + 8, wm + 16 + r0, wm + 24 + r0};
#pragma unroll
        for (int q = 0; q < 4; q++) {
            a1r[q] = asrc[hsel * 128 + rws[q]] * LOG2E;
            a2r[q] = adst[hsel * 128 + rws[q]] * LOG2E;
        }
        float* red = (float*)smh;   // reuse smem
#pragma unroll
        for (int n8 = 0; n8 < N8; n8++) {
            float s1lo = a1r[0] * acc[0][n8][0] + a1r[1] * acc[0][n8][2] +
                         a1r[2] * acc[1][n8][0] + a1r[3] * acc[1][n8][2];
            float s1hi = a1r[0] * acc[0][n8][1] + a1r[1] * acc[0][n8][3] +
                         a1r[2] * acc[1][n8][1] + a1r[3] * acc[1][n8][3];
            float s2lo = a2r[0] * acc[0][n8][0] + a2r[1] * acc[0][n8][2] +
                         a2r[2] * acc[1][n8][0] + a2r[3] * acc[1][n8][2];
            float s2hi = a2r[0] * acc[0][n8][1] + a2r[1] * acc[0][n8][3] +
                         a2r[2] * acc[1][n8][1] + a2r[3] * acc[1][n8][3];
#pragma unroll
            for (int o = 4; o < 32; o <<= 1) {
                s1lo += __shfl_xor_sync(0xffffffffu, s1lo, o);
                s1hi += __shfl_xor_sync(0xffffffffu, s1hi, o);
                s2lo += __shfl_xor_sync(0xffffffffu, s2lo, o);
                s2hi += __shfl_xor_sync(0xffffffffu, s2hi, o);
            }
            if (lane < 4) {
                int col = wn + n8 * 8 + lane * 2;
                red[(mw * TN + col) * 2 + 0] = s1lo;
                red[(mw * TN + col) * 2 + 1] = s2lo;
                red[(mw * TN + col + 1) * 2 + 0] = s1hi;
                red[(mw * TN + col + 1) * 2 + 1] = s2hi;
            }
        }
        __syncthreads();
        if (tid < TN) {
            float s1 = 0.f, s2 = 0.f;
#pragma unroll
            for (int m = 0; m < MW; m++) {
                s1 += red[(m * TN + tid) * 2 + 0];
                s2 += red[(m * TN + tid) * 2 + 1];
            }
            s1g[(size_t)z * 1024 + n0 + tid] = s1;
            s2g[(size_t)z * 1024 + n0 + tid] = s2;
        }
    }
}

// ---------------- pipelined HMMA fused attention ------------------------------
// scores pre-scaled by log2e: p = bit ? ex2(lrelu(s1+s2) - 8*log2e) : 0
#define APAD 72
template <int MODE>
__global__ __launch_bounds__(256) void at_k(const __half* __restrict__ hT,
                                            const float* __restrict__ s1g,
                                            const float* __restrict__ s2g,
                                            const unsigned* __restrict__ maskP,
                                            void* __restrict__ outp) {
    const int TM = (MODE == 0) ? 128 : 64;
    const int MW = TM / 32;
    const int NW = 8 / MW;
    const int NSP = 128 / NW;
    const int N8 = NSP / 8;
    const int SC = TM / 8;

    extern __shared__ char smraw[];
    __half* Ps = (__half*)smraw;
    __half* Vs = Ps + 2 * TM * APAD;
    float* s1s = (float*)(Vs + 2 * 128 * APAD);
    float* ds = s1s + TM;
    float* s2s = ds + TM;

    int tid = threadIdx.x, bx = blockIdx.x, z = blockIdx.z;
    int b, h;
    if (MODE == 0) { b = z >> 3; h = z & 7; }
    else { b = z; h = 0; }
    int i0 = bx * TM;
    const __half* hz = hT + (size_t)z * 131072;

    ((float4*)s2s)[tid] = ((const float4*)(s2g + (size_t)z * 1024))[tid];
    if (tid < TM) s1s[tid] = s1g[(size_t)z * 1024 + i0 + tid];
    __syncthreads();

    int w = tid >> 5, lane = tid & 31;
    int mw = w % MW, nw = w / MW;
    int wm = mw * 32, wn = nw * NSP;
    int ar = (lane & 7) | (((lane >> 3) & 1) << 3);
    int akh = (lane >> 4) << 3;
    int bn = ((lane >> 4) << 3) | (lane & 7);
    int bkh = ((lane >> 3) & 1) << 3;

    // strided-row mask base: maskP[((b*8+ib)*8+w)*512 + jp]
    int ib = (MODE == 0) ? bx : (bx >> 1);
    int hb = (MODE == 0) ? 0 : ((bx & 1) << 4);
    const unsigned* maskb = maskP + (((size_t)(b * 8 + ib)) * 8 + w) * 512;

    float acc[2][N8][4];
#pragma unroll
    for (int mt = 0; mt < 2; mt++)
#pragma unroll
        for (int n8 = 0; n8 < N8; n8++)
#pragma unroll
            for (int e = 0; e < 4; e++) acc[mt][n8][e] = 0.f;
    float dl[SC];
#pragma unroll
    for (int s = 0; s < SC; s++) dl[s] = 0.f;

    auto issueV = [&](int buf, int j0) {
        __half* vb = Vs + buf * 128 * APAD;
#pragma unroll
        for (int q = 0; q < 4; q++) {
            int f = tid + q * 256;
            int row = f >> 3, c8 = f & 7;
            cpa16(&vb[row * APAD + c8 * 8],
                  hz + (size_t)row * 1024 + j0 + c8 * 8);
        }
        cpa_commit();
    };
    auto loadMaskW = [&](int j0) -> unsigned {
        return maskb[(j0 >> 1) + lane];
    };
    auto buildP = [&](int buf, int j0, unsigned m) {
        __half* pb = Ps + buf * TM * APAD;
        float s2a = s2s[j0 + 2 * lane];
        float s2b = s2s[j0 + 2 * lane + 1];
#pragma unroll
        for (int s = 0; s < SC; s++) {
            int i = w + s * 8;
            unsigned two = (m >> (2 * s + hb)) & 3u;
            float s1v = s1s[i];
            float e1 = s1v + s2a;
            e1 = fmaxf(e1, ALPHA * e1);
            float e2 = s1v + s2b;
            e2 = fmaxf(e2, ALPHA * e2);
            float p1 = (two & 1u) ? ex2a(e1 - EXPSH) : 0.f;
            float p2 = (two & 2u) ? ex2a(e2 - EXPSH) : 0.f;
            *(half2*)&pb[i * APAD + 2 * lane] = __floats2half2_rn(p1, p2);
            dl[s] += p1 + p2;
        }
    };

    unsigned mpre = loadMaskW(0);
    issueV(0, 0);
    buildP(0, 0, mpre);

    for (int t = 0; t < 16; t++) {
        int cb = t & 1, nb = cb ^ 1;
        cpa_wait0();
        __syncthreads();
        if (t < 15) {
            issueV(nb, (t + 1) * 64);
            mpre = loadMaskW((t + 1) * 64);
        }
        const __half* pb = Ps + cb * TM * APAD;
        const __half* vb = Vs + cb * 128 * APAD;
#pragma unroll
        for (int kk = 0; kk < 64; kk += 16) {
            unsigned af[2][4], bf[N8 / 2][4];
            ldsm4(af[0], &pb[(wm + ar) * APAD + kk + akh]);
            ldsm4(af[1], &pb[(wm + 16 + ar) * APAD + kk + akh]);
#pragma unroll
            for (int np = 0; np < N8 / 2; np++)
                ldsm4(bf[np], &vb[(wn + np * 16 + bn) * APAD + kk + bkh]);
#pragma unroll
            for (int mt = 0; mt < 2; mt++)
#pragma unroll
                for (int n8 = 0; n8 < N8; n8++)
                    mma16816(acc[mt][n8], af[mt], &bf[n8 >> 1][(n8 & 1) * 2],
                             acc[mt][n8]);
        }
        if (t < 15) buildP(nb, (t + 1) * 64, mpre);
    }

#pragma unroll
    for (int s = 0; s < SC; s++) {
        float v = dl[s];
#pragma unroll
        for (int o = 16; o; o >>= 1) v += __shfl_xor_sync(0xffffffffu, v, o);
        if (lane == 0) ds[s * 8 + w] = v;
    }
    __syncthreads();

    int r0 = lane >> 2, cc = (lane & 3) * 2;
#pragma unroll
    for (int mt = 0; mt < 2; mt++)
#pragma unroll
        for (int n8 = 0; n8 < N8; n8++) {
            int row0 = wm + mt * 16 + r0, row1 = row0 + 8;
            int col = wn + n8 * 8 + cc;
            float inv0 = 1.f / ds[row0], inv1 = 1.f / ds[row1];
            float f0 = acc[mt][n8][0] * inv0, f1 = acc[mt][n8][1] * inv0;
            float f2 = acc[mt][n8][2] * inv1, f3 = acc[mt][n8][3] * inv1;
            if (MODE == 0) {
                f0 = f0 > 0.f ? f0 : expm1f(f0);
                f1 = f1 > 0.f ? f1 : expm1f(f1);
                f2 = f2 > 0.f ? f2 : expm1f(f2);
                f3 = f3 > 0.f ? f3 : expm1f(f3);
                __half* x1 = (__half*)outp;
                *(half2*)&x1[((size_t)b * 1024 + i0 + row0) * 1024 + h * 128 + col] =
                    __floats2half2_rn(f0, f1);
                *(half2*)&x1[((size_t)b * 1024 + i0 + row1) * 1024 + h * 128 + col] =
                    __floats2half2_rn(f2, f3);
            } else {
                float* o2 = (float*)outp;
                *(float2*)&o2[((size_t)b * 1024 + i0 + row0) * 128 + col] =
                    make_float2(f0, f1);
                *(float2*)&o2[((size_t)b * 1024 + i0 + row1) * 128 + col] =
                    make_float2(f2, f3);
            }
        }
}

// ---------------- final fp32 gemm: relu((linp+att2+lin_b) @ ln_wT + ln_b) ----
__global__ void __launch_bounds__(256)
final_k(const float* __restrict__ A0, const float* __restrict__ B0,
        float* __restrict__ C0, const float* __restrict__ add,
        const float* __restrict__ biasA, const float* __restrict__ biasC) {
    const int BK = 32, BM = 64, RM = 4;
    __shared__ float As[BK][BM + 4];
    __shared__ float Bs[BK][128 + 4];
    int mblk = blockIdx.x * BM;
    int tid = threadIdx.x;
    int tx = tid % 16, ty = tid / 16;
    u64 acc[RM][4];
#pragma unroll
    for (int r = 0; r < RM; r++)
#pragma unroll
        for (int c = 0; c < 4; c++) acc[r][c] = 0ull;

    for (int k0 = 0; k0 < 128; k0 += BK) {
#pragma unroll
        for (int q = 0; q < BM / 32; q++) {
            int f = tid + q * 256;
            int m = f >> 3;
            int kk = (f & 7) * 4;
            const float* ap = A0 + (size_t)(mblk + m) * 128 + (k0 + kk);
            const float* dp = add + (size_t)(mblk + m) * 128 + (k0 + kk);
            const float* bp = biasA + (k0 + kk);
            float4 v;
            v.x = ap[0] + dp[0] + bp[0];
            v.y = ap[1] + dp[1] + bp[1];
            v.z = ap[2] + dp[2] + bp[2];
            v.w = ap[3] + dp[3] + bp[3];
            As[kk + 0][m] = v.x;
            As[kk + 1][m] = v.y;
            As[kk + 2][m] = v.z;
            As[kk + 3][m] = v.w;
        }
#pragma unroll
        for (int q = 0; q < 4; q++) {
            int f = tid + q * 256;
            int kk = f >> 5;
            int nn = (f & 31) * 4;
            *(float4*)&Bs[kk][nn] = *(const float4*)(B0 + (size_t)(k0 + kk) * 128 + nn);
        }
        __syncthreads();
#pragma unroll 8
        for (int kk = 0; kk < BK; kk++) {
            u64 as_[RM];
            float4 av = *(const float4*)&As[kk][ty * RM];
            as_[0] = splat2(av.x);
            as_[1] = splat2(av.y);
            as_[2] = splat2(av.z);
            as_[3] = splat2(av.w);
            ulonglong2 b0 = *(const ulonglong2*)&Bs[kk][tx * 4];
            ulonglong2 b1 = *(const ulonglong2*)&Bs[kk][64 + tx * 4];
            u64 bs_[4] = {b0.x, b0.y, b1.x, b1.y};
#pragma unroll
            for (int r = 0; r < RM; r++)
#pragma unroll
                for (int c = 0; c < 4; c++) acc[r][c] = fma2(as_[r], bs_[c], acc[r][c]);
        }
        __syncthreads();
    }
#pragma unroll
    for (int r = 0; r < RM; r++) {
        int gm = mblk + ty * RM + r;
        float* crow = C0 + (size_t)gm * 128;
        float2 p0 = unpack2(acc[r][0]);
        float2 p1 = unpack2(acc[r][1]);
        float2 p2 = unpack2(acc[r][2]);
        float2 p3 = unpack2(acc[r][3]);
        float v[8] = {p0.x, p0.y, p1.x, p1.y, p2.x, p2.y, p3.x, p3.y};
#pragma unroll
        for (int c = 0; c < 4; c++) {
            v[c] = v[c] + biasC[tx * 4 + c];
            v[c] = v[c] > 0.f ? v[c] : 0.f;
            v[c + 4] = v[c + 4] + biasC[64 + tx * 4 + c];
            v[c + 4] = v[c + 4] > 0.f ? v[c + 4] : 0.f;
        }
        *(float4*)&crow[tx * 4] = make_float4(v[0], v[1], v[2], v[3]);
        *(float4*)&crow[64 + tx * 4] = make_float4(v[4], v[5], v[6], v[7]);
    }
}

// ---------------- launch ------------------------------------------------------
extern "C" void kernel_launch(void* const* d_in, const int* in_sizes, int n_in,
                              void* d_out, int out_size) {
    (void)in_sizes; (void)n_in; (void)out_size;
    const float* inputs = (const float*)d_in[0];
    const int* adj = (const int*)d_in[1];
    const float* W_att = (const float*)d_in[3];
    const float* a_src = (const float*)d_in[4];
    const float* a_dst = (const float*)d_in[5];
    const float* W_out = (const float*)d_in[6];
    const float* ao_src = (const float*)d_in[7];
    const float* ao_dst = (const float*)d_in[8];
    const float* lin_w = (const float*)d_in[9];
    const float* lin_b = (const float*)d_in[10];
    const float* ln_w = (const float*)d_in[11];
    const float* ln_b = (const float*)d_in[12];

    __half *p_in16, *p_wattT, *p_h1T, *p_x1, *p_woutT, *p_linw16, *p_h2T;
    float *p_linp, *p_att2, *p_s1, *p_s2, *p_s1b, *p_s2b, *p_ln_wT;
    unsigned* p_mask;
    cudaGetSymbolAddress((void**)&p_in16, g_in16);
    cudaGetSymbolAddress((void**)&p_wattT, g_wattT);
    cudaGetSymbolAddress((void**)&p_h1T, g_h1T);
    cudaGetSymbolAddress((void**)&p_x1, g_x1);
    cudaGetSymbolAddress((void**)&p_woutT, g_woutT);
    cudaGetSymbolAddress((void**)&p_linw16, g_linw16);
    cudaGetSymbolAddress((void**)&p_h2T, g_h2T);
    cudaGetSymbolAddress((void**)&p_linp, g_linp);
    cudaGetSymbolAddress((void**)&p_att2, g_att2);
    cudaGetSymbolAddress((void**)&p_s1, g_s1);
    cudaGetSymbolAddress((void**)&p_s2, g_s2);
    cudaGetSymbolAddress((void**)&p_s1b, g_s1b);
    cudaGetSymbolAddress((void**)&p_s2b, g_s2b);
    cudaGetSymbolAddress((void**)&p_ln_wT, g_ln_wT);
    cudaGetSymbolAddress((void**)&p_mask, g_mask);

    const int AT0_SMEM = (2 * 128 * APAD + 2 * 128 * APAD) * 2 + (128 + 128 + 1024) * 4;
    const int AT1_SMEM = (2 * 64 * APAD + 2 * 128 * APAD) * 2 + (64 + 64 + 1024) * 4;
    const int TG0_SMEM = 2 * (128 + 128) * 72 * 2;   // 73728
    const int TG1_SMEM = 2 * (128 + 64) * 72 * 2;    // 55296
    const int TG2_SMEM = 2 * (64 + 128) * 72 * 2;    // 55296
    cudaFuncSetAttribute(at_k<0>, cudaFuncAttributeMaxDynamicSharedMemorySize,
                         AT0_SMEM);
    cudaFuncSetAttribute(at_k<1>, cudaFuncAttributeMaxDynamicSharedMemorySize,
                         AT1_SMEM);
    cudaFuncSetAttribute(tg_k<0>, cudaFuncAttributeMaxDynamicSharedMemorySize,
                         TG0_SMEM);
    cudaFuncSetAttribute(tg_k<1>, cudaFuncAttributeMaxDynamicSharedMemorySize,
                         TG1_SMEM);
    cudaFuncSetAttribute(tg_k<2>, cudaFuncAttributeMaxDynamicSharedMemorySize,
                         TG2_SMEM);

    // order keeps at_k<0> at launch index 3 (ncu capture slot)
    prep_a_k<<<2576, 256>>>(inputs, p_in16, W_att, p_wattT, W_out, p_woutT,
                            ln_w, p_ln_wT, lin_w, p_linw16);                 // 0
    tg_k<0><<<dim3(8, 1, 64), 256, TG0_SMEM>>>(p_wattT, p_in16, p_h1T,
                                               a_src, a_dst, p_s1, p_s2);    // 1
    packadj_k<<<1024, 256>>>(adj, p_mask);                                   // 2
    at_k<0><<<dim3(8, 1, 64), 256, AT0_SMEM>>>(p_h1T, p_s1, p_s2, p_mask,
                                               p_x1);                        // 3
    tg_k<1><<<dim3(16, 1, 8), 256, TG1_SMEM>>>(p_woutT, p_x1, p_h2T,
                                               ao_src, ao_dst, p_s1b, p_s2b); // 4
    tg_k<2><<<dim3(128, 1, 1), 256, TG2_SMEM>>>(p_x1, p_linw16, p_linp,
                                                nullptr, nullptr, nullptr,
                                                nullptr);                    // 5
    at_k<1><<<dim3(16, 1, 8), 256, AT1_SMEM>>>(p_h2T, p_s1b, p_s2b, p_mask,
                                               p_att2);                      // 6
    final_k<<<128, 256>>>(p_linp, p_ln_wT, (float*)d_out, p_att2, lin_b, ln_b); // 7
}